// round 9
// baseline (speedup 1.0000x reference)
#include <cuda_runtime.h>
#include <cstdint>

#define N_INP 128
#define N_HID 512
#define N_OUT 256
#define N_HEADS 64
#define N_SM 4
#define EPS_GN 1e-5f
#define TINY 1e-14f

// scratch (device globals; allocation-free)
__device__ float g_y[N_HEADS * N_HID];           // pre-GN l1 output
__device__ float g_h1[N_HEADS * N_HID];          // post GN+softplus
__device__ float g_z[N_SM * N_HEADS * N_OUT];    // raw z before GN/softmax
__device__ float g_scalar[N_HEADS * N_OUT];      // ws row sums
__device__ float g_lp[N_OUT];                    // last_prod
__device__ int   g_cnt[N_HEADS];                 // producer completion counters (reset by K5)
__device__ int   g_ready[N_HEADS];               // h1 ready flags (reset by K5)

__device__ __forceinline__ float warp_sum(float v) {
#pragma unroll
    for (int o = 16; o > 0; o >>= 1) v += __shfl_xor_sync(0xffffffffu, v, o);
    return v;
}
__device__ __forceinline__ float warp_prod(float v) {
#pragma unroll
    for (int o = 16; o > 0; o >>= 1) v *= __shfl_xor_sync(0xffffffffu, v, o);
    return v;
}
__device__ __forceinline__ float warp_max(float v) {
#pragma unroll
    for (int o = 16; o > 0; o >>= 1) v = fmaxf(v, __shfl_xor_sync(0xffffffffu, v, o));
    return v;
}
__device__ __forceinline__ float2 warp_sum2(float2 v) {
#pragma unroll
    for (int o = 16; o > 0; o >>= 1) {
        v.x += __shfl_xor_sync(0xffffffffu, v.x, o);
        v.y += __shfl_xor_sync(0xffffffffu, v.y, o);
    }
    return v;
}
__device__ __forceinline__ float4 warp_sum4(float4 v) {
#pragma unroll
    for (int o = 16; o > 0; o >>= 1) {
        v.x += __shfl_xor_sync(0xffffffffu, v.x, o);
        v.y += __shfl_xor_sync(0xffffffffu, v.y, o);
        v.z += __shfl_xor_sync(0xffffffffu, v.z, o);
        v.w += __shfl_xor_sync(0xffffffffu, v.w, o);
    }
    return v;
}
__device__ __forceinline__ float2 block_sum2(float2 v, float2* red2) {
    int lane = threadIdx.x & 31, warp = threadIdx.x >> 5;
    int nw = blockDim.x >> 5;
    v = warp_sum2(v);
    if (lane == 0) red2[warp] = v;
    __syncthreads();
    float2 r = (threadIdx.x < nw) ? red2[threadIdx.x] : make_float2(0.f, 0.f);
    if (warp == 0) {
        r = warp_sum2(r);
        if (lane == 0) red2[0] = r;
    }
    __syncthreads();
    float2 out = red2[0];
    __syncthreads();
    return out;
}

// ---------------------------------------------------------------------------
// KM: merged streaming kernel. 1552 blocks x 512 threads.
//   bid 0..255    : w1 producers (h = bid>>2, quarter = bid&3) + GN1 tail
//   bid 256..511  : ws row sums (64 rows/block)
//   bid 512..527  : last_prod
//   bid 528..1551 : w2 consumers (spin on g_ready[h])
// ---------------------------------------------------------------------------
__global__ __launch_bounds__(512) void KM(
    const float* __restrict__ x, const float* __restrict__ qw,
    const float* __restrict__ w1, const float* __restrict__ g1g,
    const float* __restrict__ g1b, const float* __restrict__ w2,
    const float* __restrict__ ws, const float* __restrict__ last)
{
    int bid = blockIdx.x;
    int tid = threadIdx.x;
    int warp = tid >> 5, lane = tid & 31;

    if (bid < 256) {
        // ---------------- producer: one quarter (128 rows) of w1 for head h
        int h = bid >> 2;
        int q = bid & 3;
        __shared__ float qws[N_INP];
        __shared__ float subs[N_INP];
        __shared__ float2 red2[32];
        __shared__ int isLast;

        const float* w1h = w1 + (size_t)h * N_HID * N_INP;
        int r0 = q * 128 + warp * 8;

        // prefetch this warp's 8 w1 rows FIRST (independent of sub)
        float4 wv[8];
#pragma unroll
        for (int i = 0; i < 8; i++)
            wv[i] = __ldcs((const float4*)(w1h + (size_t)(r0 + i) * N_INP + lane * 4));

        if (tid < N_INP) qws[tid] = qw[h * N_INP + tid];
        __syncthreads();

        float q0 = qws[lane * 4 + 0], q1 = qws[lane * 4 + 1],
              q2 = qws[lane * 4 + 2], q3 = qws[lane * 4 + 3];
#pragma unroll
        for (int g = 0; g < 2; g++) {
            int rr = warp * 8 + g * 4;
            float p[4];
#pragma unroll
            for (int i = 0; i < 4; i++) {
                float4 xv = *(const float4*)(x + (rr + i) * N_INP + lane * 4);
                p[i] = xv.x * q0 + xv.y * q1 + xv.z * q2 + xv.w * q3;
            }
            float4 s = warp_sum4(make_float4(p[0], p[1], p[2], p[3]));
            if (lane == 0) *(float4*)(subs + rr) = s;
        }
        __syncthreads();

        float s0 = subs[lane * 4 + 0], s1 = subs[lane * 4 + 1],
              s2 = subs[lane * 4 + 2], s3 = subs[lane * 4 + 3];
#pragma unroll
        for (int g = 0; g < 2; g++) {
            float p[4];
#pragma unroll
            for (int i = 0; i < 4; i++) {
                float4 w4 = wv[g * 4 + i];
                p[i] = w4.x * s0 + w4.y * s1 + w4.z * s2 + w4.w * s3;
            }
            float4 acc = warp_sum4(make_float4(p[0], p[1], p[2], p[3]));
            if (lane == 0) *(float4*)(g_y + h * N_HID + r0 + g * 4) = acc;
        }

        // GN1 tail: last-arriving block for this head does GN+softplus
        __threadfence();
        if (tid == 0) isLast = (atomicAdd(&g_cnt[h], 1) == 3);
        __syncthreads();
        if (isLast) {
            __threadfence();
            float v = __ldcg(g_y + h * N_HID + tid);
            float2 ss = block_sum2(make_float2(v, v * v), red2);
            float mu = ss.x * (1.f / N_HID);
            float var = ss.y * (1.f / N_HID) - mu * mu;
            float rstd = rsqrtf(var + EPS_GN);
            float t = (v - mu) * rstd * g1g[h * N_HID + tid] + g1b[h * N_HID + tid];
            float sp = fmaxf(t, 0.f) + log1pf(expf(-fabsf(t)));
            g_h1[h * N_HID + tid] = sp;
            __threadfence();
            __syncthreads();
            if (tid == 0) *(volatile int*)(g_ready + h) = 1;
        }
        return;
    }

    if (bid < 512) {
        // ---------------- ws row sums: 64 rows per block
        int r0 = (bid - 256) * 64 + warp * 4;
        float p[4];
#pragma unroll
        for (int i = 0; i < 4; i++) {
            const float* pr = ws + (size_t)(r0 + i) * N_OUT + lane * 4;
            float4 a = __ldcs((const float4*)(pr));
            float4 b = __ldcs((const float4*)(pr + 128));
            p[i] = a.x + a.y + a.z + a.w + b.x + b.y + b.z + b.w;
        }
        float4 s = warp_sum4(make_float4(p[0], p[1], p[2], p[3]));
        if (lane == 0) *(float4*)(g_scalar + r0) = s;
        return;
    }

    if (bid < 528) {
        // ---------------- last_prod
        int o = (bid - 512) * 16 + warp;
        float v = last[o * N_HEADS + lane] * last[o * N_HEADS + 32 + lane];
        v = warp_prod(v);
        if (lane == 0) g_lp[o] = v;
        return;
    }

    // ---------------- w2 consumer: bid-528 = sh*4 + quarter
    {
        int cb = bid - 528;
        int sh = cb >> 2;
        int q  = cb & 3;
        int h  = sh & 63;
        __shared__ float h1s[N_HID];

        if (tid == 0) {
            while (*(volatile int*)(g_ready + h) == 0) __nanosleep(64);
        }
        __syncthreads();
        __threadfence();

        h1s[tid] = __ldcg(g_h1 + h * N_HID + tid);
        __syncthreads();

        float ha[4][4];
#pragma unroll
        for (int k = 0; k < 4; k++) {
            ha[k][0] = h1s[k * 128 + lane * 4 + 0];
            ha[k][1] = h1s[k * 128 + lane * 4 + 1];
            ha[k][2] = h1s[k * 128 + lane * 4 + 2];
            ha[k][3] = h1s[k * 128 + lane * 4 + 3];
        }

        const float* wp = w2 + (size_t)sh * N_OUT * N_HID;
        int r0 = q * 64 + warp * 4;
        float p[4];
#pragma unroll
        for (int i = 0; i < 4; i++) {
            const float* row = wp + (size_t)(r0 + i) * N_HID + lane * 4;
            float acc = 0.f;
#pragma unroll
            for (int k = 0; k < 4; k++) {
                float4 wv = __ldcs((const float4*)(row + k * 128));
                acc += wv.x * ha[k][0] + wv.y * ha[k][1] + wv.z * ha[k][2] + wv.w * ha[k][3];
            }
            p[i] = acc;
        }
        float4 s = warp_sum4(make_float4(p[0], p[1], p[2], p[3]));
        if (lane == 0) *(float4*)(g_z + sh * N_OUT + r0) = s;
    }
}

// ---------------------------------------------------------------------------
// K5: fused epilogue. 64 blocks x 1024 threads. thread = (s, o).
// Also resets g_cnt/g_ready for the next graph replay.
// ---------------------------------------------------------------------------
__global__ __launch_bounds__(1024) void K5(
    const float* __restrict__ g2g, const float* __restrict__ g2b,
    const float* __restrict__ woo, float* __restrict__ out)
{
    int h = blockIdx.x;
    int tid = threadIdx.x;
    int s = tid >> 8;          // 0..3
    int o = tid & 255;
    int warp = tid >> 5, lane = tid & 31;
    int segw = s * 8;

    __shared__ float2 red2[32];
    __shared__ float red[32];
    __shared__ float smv[N_SM * N_OUT];
    __shared__ float redg[8];

    if (tid == 0) { g_cnt[h] = 0; g_ready[h] = 0; }

    int idx = (((s * N_HEADS) + h) << 8) + o;
    float z = g_z[idx];

    {
        float2 v = warp_sum2(make_float2(z, z * z));
        if (lane == 0) red2[warp] = v;
    }
    __syncthreads();
    float sum = 0.f, sq = 0.f;
#pragma unroll
    for (int i = 0; i < 8; i++) {
        float2 r = red2[segw + i];
        sum += r.x; sq += r.y;
    }
    float mu = sum * (1.f / N_OUT);
    float var = sq * (1.f / N_OUT) - mu * mu;
    float rstd = rsqrtf(var + EPS_GN);
    float zn = (z - mu) * rstd * g2g[idx] + g2b[idx];

    {
        float m = warp_max(zn);
        if (lane == 0) red[warp] = m;
    }
    __syncthreads();
    float zmax = -3.4e38f;
#pragma unroll
    for (int i = 0; i < 8; i++) zmax = fmaxf(zmax, red[segw + i]);

    float e = expf(zn - zmax);
    __syncthreads();
    {
        float d = warp_sum(e);
        if (lane == 0) red[warp] = d;
    }
    __syncthreads();
    float denom = 0.f;
#pragma unroll
    for (int i = 0; i < 8; i++) denom += red[segw + i];

    smv[tid] = e / denom;
    __syncthreads();

    if (s == 0) {
        float osm = smv[o] + smv[256 + o] + smv[512 + o] + smv[768 + o];
        float part = woo[h * 512 + o] * g_lp[o] + woo[h * 512 + N_OUT + o] * osm;
        float g = warp_sum(part);
        if (lane == 0) redg[warp] = g;
        smv[o] = osm;
    }
    __syncthreads();
    if (s == 0) {
        float logit = redg[0] + redg[1] + redg[2] + redg[3] +
                      redg[4] + redg[5] + redg[6] + redg[7];
        float on_off = 1.f / (1.f + expf(-logit));
        float osm = smv[o];
        float v = on_off * osm;
        out[o * N_HEADS + h] = fmaxf(v, TINY);
        float sc = v * g_scalar[h * N_OUT + o];
        out[N_OUT * N_HEADS + o * N_HEADS + h] = (fabsf(sc) <= TINY) ? TINY : sc;
    }
}

extern "C" void kernel_launch(void* const* d_in, const int* in_sizes, int n_in,
                              void* d_out, int out_size)
{
    const float* x    = (const float*)d_in[0];
    const float* last = (const float*)d_in[1];
    const float* qw   = (const float*)d_in[2];
    const float* w1   = (const float*)d_in[3];
    const float* g1g  = (const float*)d_in[4];
    const float* g1b  = (const float*)d_in[5];
    const float* w2   = (const float*)d_in[6];
    const float* g2g  = (const float*)d_in[7];
    const float* g2b  = (const float*)d_in[8];
    const float* ws   = (const float*)d_in[9];
    const float* woo  = (const float*)d_in[10];
    float* out = (float*)d_out;

    KM<<<1552, 512>>>(x, qw, w1, g1g, g1b, w2, ws, last);
    K5<<<N_HEADS, 1024>>>(g2g, g2b, woo, out);
}

// round 15
// speedup vs baseline: 1.2656x; 1.2656x over previous
#include <cuda_runtime.h>
#include <cstdint>

#define N_INP 128
#define N_HID 512
#define N_OUT 256
#define N_HEADS 64
#define N_SM 4
#define EPS_GN 1e-5f
#define TINY 1e-14f

// scratch (device globals; allocation-free)
__device__ float g_y[N_HEADS * N_HID];           // pre-GN l1 output
__device__ float g_z[N_SM * N_HEADS * N_OUT];    // raw z before GN/softmax
__device__ float g_scalar[N_HEADS * N_OUT];      // ws row sums
__device__ float g_lp[N_OUT];                    // last_prod

__device__ __forceinline__ float warp_sum(float v) {
#pragma unroll
    for (int o = 16; o > 0; o >>= 1) v += __shfl_xor_sync(0xffffffffu, v, o);
    return v;
}
__device__ __forceinline__ float warp_prod(float v) {
#pragma unroll
    for (int o = 16; o > 0; o >>= 1) v *= __shfl_xor_sync(0xffffffffu, v, o);
    return v;
}
__device__ __forceinline__ float warp_max(float v) {
#pragma unroll
    for (int o = 16; o > 0; o >>= 1) v = fmaxf(v, __shfl_xor_sync(0xffffffffu, v, o));
    return v;
}
__device__ __forceinline__ float2 warp_sum2(float2 v) {
#pragma unroll
    for (int o = 16; o > 0; o >>= 1) {
        v.x += __shfl_xor_sync(0xffffffffu, v.x, o);
        v.y += __shfl_xor_sync(0xffffffffu, v.y, o);
    }
    return v;
}
__device__ __forceinline__ float4 warp_sum4(float4 v) {
#pragma unroll
    for (int o = 16; o > 0; o >>= 1) {
        v.x += __shfl_xor_sync(0xffffffffu, v.x, o);
        v.y += __shfl_xor_sync(0xffffffffu, v.y, o);
        v.z += __shfl_xor_sync(0xffffffffu, v.z, o);
        v.w += __shfl_xor_sync(0xffffffffu, v.w, o);
    }
    return v;
}
__device__ __forceinline__ float2 block_sum2(float2 v, float2* red2) {
    int lane = threadIdx.x & 31, warp = threadIdx.x >> 5;
    int nw = blockDim.x >> 5;
    v = warp_sum2(v);
    if (lane == 0) red2[warp] = v;
    __syncthreads();
    float2 r = (threadIdx.x < nw) ? red2[threadIdx.x] : make_float2(0.f, 0.f);
    if (warp == 0) {
        r = warp_sum2(r);
        if (lane == 0) red2[0] = r;
    }
    __syncthreads();
    float2 out = red2[0];
    __syncthreads();
    return out;
}

// ---------------------------------------------------------------------------
// K1: 256 blocks (h,quarter) x 512. Prefetch first 4 w1 rows BEFORE the sub
// phase so the sub latency hides under the w1 DRAM stream.
// ---------------------------------------------------------------------------
__global__ __launch_bounds__(512) void K1(
    const float* __restrict__ x, const float* __restrict__ qw,
    const float* __restrict__ w1)
{
    int h = blockIdx.x >> 2;
    int q = blockIdx.x & 3;
    int tid = threadIdx.x;
    int warp = tid >> 5, lane = tid & 31;

    __shared__ float qws[N_INP];
    __shared__ float subs[N_INP];

    const float* w1h = w1 + (size_t)h * N_HID * N_INP;
    int r0 = q * 128 + warp * 8;

    // prefetch group-0 rows (independent of sub; issued before any barrier)
    float4 wv0[4];
#pragma unroll
    for (int i = 0; i < 4; i++)
        wv0[i] = __ldcs((const float4*)(w1h + (size_t)(r0 + i) * N_INP + lane * 4));

    if (tid < N_INP) qws[tid] = qw[h * N_INP + tid];
    __syncthreads();

    float q0 = qws[lane * 4 + 0], q1 = qws[lane * 4 + 1],
          q2 = qws[lane * 4 + 2], q3 = qws[lane * 4 + 3];

#pragma unroll
    for (int g = 0; g < 2; g++) {
        int rr = warp * 8 + g * 4;
        float p[4];
#pragma unroll
        for (int i = 0; i < 4; i++) {
            float4 xv = *(const float4*)(x + (rr + i) * N_INP + lane * 4);
            p[i] = xv.x * q0 + xv.y * q1 + xv.z * q2 + xv.w * q3;
        }
        float4 s = warp_sum4(make_float4(p[0], p[1], p[2], p[3]));
        if (lane == 0) *(float4*)(subs + rr) = s;
    }
    __syncthreads();

    float s0 = subs[lane * 4 + 0], s1 = subs[lane * 4 + 1],
          s2 = subs[lane * 4 + 2], s3 = subs[lane * 4 + 3];

    // issue group-1 loads first, then consume group-0 prefetches
    float4 wv1[4];
#pragma unroll
    for (int i = 0; i < 4; i++)
        wv1[i] = __ldcs((const float4*)(w1h + (size_t)(r0 + 4 + i) * N_INP + lane * 4));

    {
        float p[4];
#pragma unroll
        for (int i = 0; i < 4; i++)
            p[i] = wv0[i].x * s0 + wv0[i].y * s1 + wv0[i].z * s2 + wv0[i].w * s3;
        float4 acc = warp_sum4(make_float4(p[0], p[1], p[2], p[3]));
        if (lane == 0) *(float4*)(g_y + h * N_HID + r0) = acc;
    }
    {
        float p[4];
#pragma unroll
        for (int i = 0; i < 4; i++)
            p[i] = wv1[i].x * s0 + wv1[i].y * s1 + wv1[i].z * s2 + wv1[i].w * s3;
        float4 acc = warp_sum4(make_float4(p[0], p[1], p[2], p[3]));
        if (lane == 0) *(float4*)(g_y + h * N_HID + r0 + 4) = acc;
    }
}

// ---------------------------------------------------------------------------
// K3: bid<1024: GN1+softplus (in-block from g_y) then w2 quarter matmul.
//     1024<=bid<1280: ws row sums. 1280<=bid<1296: last_prod.
// 1296 blocks x 512. (Unchanged — near roofline.)
// ---------------------------------------------------------------------------
__global__ __launch_bounds__(512) void K3(
    const float* __restrict__ w2, const float* __restrict__ ws,
    const float* __restrict__ last, const float* __restrict__ g1g,
    const float* __restrict__ g1b)
{
    int bid = blockIdx.x;
    int tid = threadIdx.x;
    int warp = tid >> 5, lane = tid & 31;

    if (bid >= 1280) {
        int o = (bid - 1280) * 16 + warp;
        float v = last[o * N_HEADS + lane] * last[o * N_HEADS + 32 + lane];
        v = warp_prod(v);
        if (lane == 0) g_lp[o] = v;
        return;
    }
    if (bid >= 1024) {
        int r0 = (bid - 1024) * 64 + warp * 4;
        float p[4];
#pragma unroll
        for (int i = 0; i < 4; i++) {
            const float* pr = ws + (size_t)(r0 + i) * N_OUT + lane * 4;
            float4 a = __ldcs((const float4*)(pr));
            float4 b = __ldcs((const float4*)(pr + 128));
            p[i] = a.x + a.y + a.z + a.w + b.x + b.y + b.z + b.w;
        }
        float4 s = warp_sum4(make_float4(p[0], p[1], p[2], p[3]));
        if (lane == 0) *(float4*)(g_scalar + r0) = s;
        return;
    }

    // w2 part: bid = sh*4 + quarter
    int sh = bid >> 2;
    int q  = bid & 3;
    int h  = sh & 63;
    __shared__ float h1s[N_HID];
    __shared__ float2 red2[32];

    // GN1 + softplus in-block (blockDim == N_HID)
    {
        float v = g_y[h * N_HID + tid];
        float2 ss = block_sum2(make_float2(v, v * v), red2);
        float mu = ss.x * (1.f / N_HID);
        float var = ss.y * (1.f / N_HID) - mu * mu;
        float rstd = rsqrtf(var + EPS_GN);
        float t = (v - mu) * rstd * g1g[h * N_HID + tid] + g1b[h * N_HID + tid];
        h1s[tid] = fmaxf(t, 0.f) + log1pf(expf(-fabsf(t)));
    }
    __syncthreads();

    float ha[4][4];
#pragma unroll
    for (int k = 0; k < 4; k++) {
        ha[k][0] = h1s[k * 128 + lane * 4 + 0];
        ha[k][1] = h1s[k * 128 + lane * 4 + 1];
        ha[k][2] = h1s[k * 128 + lane * 4 + 2];
        ha[k][3] = h1s[k * 128 + lane * 4 + 3];
    }

    const float* wp = w2 + (size_t)sh * N_OUT * N_HID;
    int r0 = q * 64 + warp * 4;
    float p[4];
#pragma unroll
    for (int i = 0; i < 4; i++) {
        const float* row = wp + (size_t)(r0 + i) * N_HID + lane * 4;
        float acc = 0.f;
#pragma unroll
        for (int k = 0; k < 4; k++) {
            float4 wv = __ldcs((const float4*)(row + k * 128));
            acc += wv.x * ha[k][0] + wv.y * ha[k][1] + wv.z * ha[k][2] + wv.w * ha[k][3];
        }
        p[i] = acc;
    }
    float4 s = warp_sum4(make_float4(p[0], p[1], p[2], p[3]));
    if (lane == 0) *(float4*)(g_z + sh * N_OUT + r0) = s;
}

// ---------------------------------------------------------------------------
// K5: fused epilogue. 64 blocks x 1024 threads. thread = (s, o).
// All DRAM loads prefetched at entry; disjoint reduction buffers (one fewer
// sync). Segment = 8 warps per s.
// ---------------------------------------------------------------------------
__global__ __launch_bounds__(1024) void K5(
    const float* __restrict__ g2g, const float* __restrict__ g2b,
    const float* __restrict__ woo, float* __restrict__ out)
{
    int h = blockIdx.x;
    int tid = threadIdx.x;
    int s = tid >> 8;          // 0..3
    int o = tid & 255;
    int warp = tid >> 5, lane = tid & 31;
    int segw = s * 8;

    __shared__ float2 red2[32];
    __shared__ float redm[32];
    __shared__ float redd[32];
    __shared__ float smv[N_SM * N_OUT];
    __shared__ float redg[8];

    int idx = (((s * N_HEADS) + h) << 8) + o;

    // prefetch everything (independent addresses)
    float z  = g_z[idx];
    float gg = g2g[idx];
    float gb = g2b[idx];
    float lp = 0.f, w_a = 0.f, w_b = 0.f, scl = 0.f;
    if (s == 0) {
        lp  = g_lp[o];
        w_a = woo[h * 512 + o];
        w_b = woo[h * 512 + N_OUT + o];
        scl = g_scalar[h * N_OUT + o];
    }

    // segmented sum of (z, z^2)
    {
        float2 v = warp_sum2(make_float2(z, z * z));
        if (lane == 0) red2[warp] = v;
    }
    __syncthreads();
    float sum = 0.f, sq = 0.f;
#pragma unroll
    for (int i = 0; i < 8; i++) {
        float2 r = red2[segw + i];
        sum += r.x; sq += r.y;
    }
    float mu = sum * (1.f / N_OUT);
    float var = sq * (1.f / N_OUT) - mu * mu;
    float rstd = rsqrtf(var + EPS_GN);
    float zn = (z - mu) * rstd * gg + gb;

    // segmented max
    {
        float m = warp_max(zn);
        if (lane == 0) redm[warp] = m;
    }
    __syncthreads();
    float zmax = -3.4e38f;
#pragma unroll
    for (int i = 0; i < 8; i++) zmax = fmaxf(zmax, redm[segw + i]);

    float e = expf(zn - zmax);
    {
        float d = warp_sum(e);
        if (lane == 0) redd[warp] = d;
    }
    __syncthreads();
    float denom = 0.f;
#pragma unroll
    for (int i = 0; i < 8; i++) denom += redd[segw + i];

    smv[tid] = e / denom;
    __syncthreads();

    if (s == 0) {
        float osm = smv[o] + smv[256 + o] + smv[512 + o] + smv[768 + o];
        float part = w_a * lp + w_b * osm;
        float g = warp_sum(part);
        if (lane == 0) redg[warp] = g;
        smv[o] = osm;
    }
    __syncthreads();
    if (s == 0) {
        float logit = redg[0] + redg[1] + redg[2] + redg[3] +
                      redg[4] + redg[5] + redg[6] + redg[7];
        float on_off = 1.f / (1.f + expf(-logit));
        float osm = smv[o];
        float v = on_off * osm;
        out[o * N_HEADS + h] = fmaxf(v, TINY);
        float sc = v * scl;
        out[N_OUT * N_HEADS + o * N_HEADS + h] = (fabsf(sc) <= TINY) ? TINY : sc;
    }
}

extern "C" void kernel_launch(void* const* d_in, const int* in_sizes, int n_in,
                              void* d_out, int out_size)
{
    const float* x    = (const float*)d_in[0];
    const float* last = (const float*)d_in[1];
    const float* qw   = (const float*)d_in[2];
    const float* w1   = (const float*)d_in[3];
    const float* g1g  = (const float*)d_in[4];
    const float* g1b  = (const float*)d_in[5];
    const float* w2   = (const float*)d_in[6];
    const float* g2g  = (const float*)d_in[7];
    const float* g2b  = (const float*)d_in[8];
    const float* ws   = (const float*)d_in[9];
    const float* woo  = (const float*)d_in[10];
    float* out = (float*)d_out;

    K1<<<256, 512>>>(x, qw, w1);
    K3<<<1296, 512>>>(w2, ws, last, g1g, g1b);
    K5<<<N_HEADS, 1024>>>(g2g, g2b, woo, out);
}